// round 1
// baseline (speedup 1.0000x reference)
#include <cuda_runtime.h>
#include <math.h>
#include <float.h>

#define A_N 33600
#define G_N 256
#define C_N 80
#define TOPK 10

// Scratch (allocation-free: __device__ globals)
__device__ float g_total_neg[A_N];
__device__ float g_scoresT[C_N * A_N];
__device__ int   g_assigned[A_N];

__device__ __forceinline__ float softplus_f(float x) {
    // matches jax.nn.softplus = logaddexp(x, 0) = max(x,0) + log1p(exp(-|x|))
    return fmaxf(x, 0.0f) + log1pf(expf(-fabsf(x)));
}

__device__ __forceinline__ bool lessvi(float v1, int i1, float v2, int i2) {
    // lexicographic (value asc, index asc) == jax.lax.top_k(-cost) ordering
    return (v1 < v2) || (v1 == v2 && i1 < i2);
}

__global__ void init_kernel() {
    int a = blockIdx.x * blockDim.x + threadIdx.x;
    if (a < A_N) g_assigned[a] = -1;
}

__global__ void totalneg_kernel(const float* __restrict__ scores) {
    int idx  = blockIdx.x * blockDim.x + threadIdx.x;
    int warp = idx >> 5;
    int lane = idx & 31;
    if (warp >= A_N) return;
    float sum = 0.0f;
    for (int c = lane; c < C_N; c += 32)
        sum += softplus_f(scores[warp * C_N + c]);
    for (int o = 16; o; o >>= 1)
        sum += __shfl_down_sync(0xffffffffu, sum, o);
    if (lane == 0) g_total_neg[warp] = sum;
}

__global__ void transpose_kernel(const float* __restrict__ scores) {
    __shared__ float tile[32][33];
    int a0 = blockIdx.x * 32, c0 = blockIdx.y * 32;
    int a = a0 + threadIdx.y, c = c0 + threadIdx.x;
    if (a < A_N && c < C_N)
        tile[threadIdx.y][threadIdx.x] = scores[a * C_N + c];
    __syncthreads();
    int ao = a0 + threadIdx.x, co = c0 + threadIdx.y;
    if (ao < A_N && co < C_N)
        g_scoresT[(size_t)co * A_N + ao] = tile[threadIdx.x][threadIdx.y];
}

__global__ __launch_bounds__(256) void simota_kernel(
    const float* __restrict__ pred_bboxes,
    const float* __restrict__ anchor_points,
    const int*   __restrict__ gt_labels,
    const float* __restrict__ gt_bboxes)
{
    const int g   = blockIdx.x;
    const int tid = threadIdx.x;

    const float gx1 = gt_bboxes[g * 4 + 0];
    const float gy1 = gt_bboxes[g * 4 + 1];
    const float gx2 = gt_bboxes[g * 4 + 2];
    const float gy2 = gt_bboxes[g * 4 + 3];
    const int   L   = gt_labels[g];

    const float cx = (gx1 + gx2) / 2.0f;
    const float cy = (gy1 + gy2) / 2.0f;
    const float rx = 2.5f * (gx2 - gx1);
    const float ry = 2.5f * (gy2 - gy1);
    const float clx = cx - rx, chx = cx + rx;
    const float cly = cy - ry, chy = cy + ry;
    const float area_g = (gx2 - gx1) * (gy2 - gy1);

    float bv[TOPK];
    int   bi[TOPK];
#pragma unroll
    for (int k = 0; k < TOPK; k++) { bv[k] = FLT_MAX; bi[k] = 0x7fffffff; }
    int cnt = 0;

    const float2* ap2  = (const float2*)anchor_points;
    const float4* pb4  = (const float4*)pred_bboxes;
    const float*  srow = g_scoresT + (size_t)L * A_N;

    for (int a = tid; a < A_N; a += 256) {
        float2 ap = ap2[a];
        float4 pb = pb4[a];

        bool inside = (ap.x >= gx1) & (ap.x <= gx2) & (ap.y >= gy1) & (ap.y <= gy2)
                    & (ap.x >= clx) & (ap.x <= chx) & (ap.y >= cly) & (ap.y <= chy);

        float ltx = fmaxf(pb.x, gx1), lty = fmaxf(pb.y, gy1);
        float rbx = fminf(pb.z, gx2), rby = fminf(pb.w, gy2);
        float w   = fmaxf(rbx - ltx, 0.0f);
        float h   = fmaxf(rby - lty, 0.0f);
        float ov  = w * h;
        float area_p = (pb.z - pb.x) * (pb.w - pb.y);
        float iou = ov / (area_p + area_g - ov + 1e-6f);

        if (inside && iou > 0.0f) cnt++;

        float s = srow[a];
        float e = expf(-fabsf(s));
        float l = log1pf(e);
        float sp_pos = fmaxf(-s, 0.0f) + l;
        float sp_neg = fmaxf( s, 0.0f) + l;
        float cls  = g_total_neg[a] + (sp_pos - sp_neg);
        float iouc = -logf(fmaxf(iou, 1e-7f));
        // cost = 1*cls + 3*iou_cost + (~inside)*1e10, without FMA contraction
        // so the rounding bucket at 1e10 matches the reference exactly.
        float cost = __fadd_rn(__fadd_rn(cls, __fmul_rn(3.0f, iouc)),
                               inside ? 0.0f : 1e10f);

        if (lessvi(cost, a, bv[TOPK - 1], bi[TOPK - 1])) {
            int p = TOPK - 1;
            while (p > 0 && lessvi(cost, a, bv[p - 1], bi[p - 1])) {
                bv[p] = bv[p - 1]; bi[p] = bi[p - 1]; p--;
            }
            bv[p] = cost; bi[p] = a;
        }
    }

    // ---- block merge: 256 * 10 candidates -> global top-10 ----
    __shared__ float sv[256 * TOPK];
    __shared__ int   si[256 * TOPK];
    __shared__ float rv[256];
    __shared__ int   ri[256];
    __shared__ int   rs[256];
    __shared__ int   sc[256];
    __shared__ int   topk_s[TOPK];

#pragma unroll
    for (int k = 0; k < TOPK; k++) {
        sv[tid * TOPK + k] = bv[k];
        si[tid * TOPK + k] = bi[k];
    }
    sc[tid] = cnt;
    __syncthreads();

    // dyn_k count reduction
    for (int off = 128; off; off >>= 1) {
        if (tid < off) sc[tid] += sc[tid + off];
        __syncthreads();
    }

    for (int r = 0; r < TOPK; r++) {
        float mv = FLT_MAX; int mi = 0x7fffffff; int ms = -1;
#pragma unroll
        for (int k = 0; k < TOPK; k++) {
            int s0 = tid * TOPK + k;
            if (lessvi(sv[s0], si[s0], mv, mi)) { mv = sv[s0]; mi = si[s0]; ms = s0; }
        }
        rv[tid] = mv; ri[tid] = mi; rs[tid] = ms;
        __syncthreads();
        for (int off = 128; off; off >>= 1) {
            if (tid < off && lessvi(rv[tid + off], ri[tid + off], rv[tid], ri[tid])) {
                rv[tid] = rv[tid + off]; ri[tid] = ri[tid + off]; rs[tid] = rs[tid + off];
            }
            __syncthreads();
        }
        if (tid == 0) {
            topk_s[r] = ri[0];
            sv[rs[0]] = FLT_MAX;
            si[rs[0]] = 0x7fffffff;
        }
        __syncthreads();
    }

    if (tid == 0) {
        int k = sc[0];
        if (k < 1) k = 1;
        if (k > TOPK) k = TOPK;
        for (int r = 0; r < k; r++)
            atomicMax(&g_assigned[topk_s[r]], g);
    }
}

__global__ void finalize_kernel(const float* __restrict__ pred_bboxes,
                                const int*   __restrict__ gt_labels,
                                const float* __restrict__ gt_bboxes,
                                float* __restrict__ out)
{
    int a = blockIdx.x * blockDim.x + threadIdx.x;
    if (a >= A_N) return;

    int  g    = g_assigned[a];
    bool pos  = (g >= 0);
    int  safe = pos ? g : 0;
    int  label = pos ? gt_labels[safe] : C_N;

    float4 gb = ((const float4*)gt_bboxes)[safe];

    // labels
    out[a] = (float)label;

    // bboxes
    float* ob = out + A_N + (size_t)a * 4;
    ob[0] = pos ? gb.x : 0.0f;
    ob[1] = pos ? gb.y : 0.0f;
    ob[2] = pos ? gb.z : 0.0f;
    ob[3] = pos ? gb.w : 0.0f;

    // scores: one-hot IoU at the assigned label
    float sc_val = 0.0f;
    if (pos) {
        float4 pb = ((const float4*)pred_bboxes)[a];
        float ltx = fmaxf(pb.x, gb.x), lty = fmaxf(pb.y, gb.y);
        float rbx = fminf(pb.z, gb.z), rby = fminf(pb.w, gb.w);
        float w = fmaxf(rbx - ltx, 0.0f);
        float h = fmaxf(rby - lty, 0.0f);
        float ov = w * h;
        float area_p = (pb.z - pb.x) * (pb.w - pb.y);
        float area_g = (gb.z - gb.x) * (gb.w - gb.y);
        sc_val = ov / (area_p + area_g - ov + 1e-6f);
    }
    float* os = out + (size_t)5 * A_N + (size_t)a * (C_N + 1);
#pragma unroll 9
    for (int c = 0; c <= C_N; c++) os[c] = 0.0f;
    if (pos) os[label] = sc_val;
}

extern "C" void kernel_launch(void* const* d_in, const int* in_sizes, int n_in,
                              void* d_out, int out_size) {
    const float* pred_scores   = (const float*)d_in[0];
    const float* pred_bboxes   = (const float*)d_in[1];
    const float* anchor_points = (const float*)d_in[2];
    const int*   gt_labels     = (const int*)  d_in[3];
    const float* gt_bboxes     = (const float*)d_in[4];
    float* out = (float*)d_out;

    init_kernel<<<(A_N + 255) / 256, 256>>>();
    totalneg_kernel<<<(A_N * 32 + 255) / 256, 256>>>(pred_scores);
    transpose_kernel<<<dim3(A_N / 32, (C_N + 31) / 32), dim3(32, 32)>>>(pred_scores);
    simota_kernel<<<G_N, 256>>>(pred_bboxes, anchor_points, gt_labels, gt_bboxes);
    finalize_kernel<<<(A_N + 255) / 256, 256>>>(pred_bboxes, gt_labels, gt_bboxes, out);
}

// round 2
// speedup vs baseline: 4.1183x; 4.1183x over previous
#include <cuda_runtime.h>
#include <math.h>
#include <float.h>

#define A_N 33600
#define G_N 256
#define C_N 80
#define TOPK 10
#define NT   512
#define SENT 0xFFFFFFFFFFFFFFFFULL

// Scratch (allocation-free: __device__ globals)
__device__ float g_total_neg[A_N];
__device__ float g_clsT[C_N * A_N];   // clsT[c][a] = total_neg[a] + (softplus(-s)-softplus(s))
__device__ int   g_assigned[A_N];

// monotone float -> uint mapping, packed with index for lexicographic (cost asc, idx asc)
__device__ __forceinline__ unsigned long long packKey(float v, unsigned idx) {
    unsigned u = __float_as_uint(v);
    u = (u & 0x80000000u) ? ~u : (u | 0x80000000u);
    return (((unsigned long long)u) << 32) | (unsigned long long)idx;
}

// ---- kernel 1: total_neg per anchor (+ init of g_assigned) ----
__global__ void totalneg_kernel(const float* __restrict__ scores) {
    int idx = blockIdx.x * blockDim.x + threadIdx.x;
    if (idx < A_N) g_assigned[idx] = -1;
    int warp = idx >> 5, lane = idx & 31;
    if (warp >= A_N) return;
    float sum = 0.0f;
    for (int c = lane; c < C_N; c += 32) {
        float x = scores[warp * C_N + c];
        sum += fmaxf(x, 0.0f) + log1pf(expf(-fabsf(x)));
    }
    for (int o = 16; o; o >>= 1) sum += __shfl_down_sync(0xffffffffu, sum, o);
    if (lane == 0) g_total_neg[warp] = sum;
}

// ---- kernel 2: transpose + fold softplus difference + total_neg ----
__global__ void clsT_kernel(const float* __restrict__ scores) {
    __shared__ float tile[32][33];
    int a0 = blockIdx.x * 32, c0 = blockIdx.y * 32;
    int a = a0 + threadIdx.y, c = c0 + threadIdx.x;
    float d = 0.0f;
    if (c < C_N) {
        float s = scores[a * C_N + c];
        float l = log1pf(expf(-fabsf(s)));
        float sp_pos = fmaxf(-s, 0.0f) + l;   // softplus(-s), reference rounding
        float sp_neg = fmaxf( s, 0.0f) + l;   // softplus(s)
        d = sp_pos - sp_neg;
    }
    tile[threadIdx.y][threadIdx.x] = d;
    __syncthreads();
    int ao = a0 + threadIdx.x, co = c0 + threadIdx.y;
    if (co < C_N)
        g_clsT[(size_t)co * A_N + ao] = g_total_neg[ao] + tile[threadIdx.x][threadIdx.y];
}

// ---- kernel 3: fused per-GT cost + dyn_k + top-10 + scatter ----
__global__ __launch_bounds__(NT) void simota_kernel(
    const float* __restrict__ pred_bboxes,
    const float* __restrict__ anchor_points,
    const int*   __restrict__ gt_labels,
    const float* __restrict__ gt_bboxes)
{
    const int g   = blockIdx.x;
    const int tid = threadIdx.x;

    const float4 gb = ((const float4*)gt_bboxes)[g];
    const float gx1 = gb.x, gy1 = gb.y, gx2 = gb.z, gy2 = gb.w;
    const int   L   = gt_labels[g];

    const float cx = (gx1 + gx2) / 2.0f;
    const float cy = (gy1 + gy2) / 2.0f;
    const float rx = 2.5f * (gx2 - gx1);
    const float ry = 2.5f * (gy2 - gy1);
    const float clx = cx - rx, chx = cx + rx;
    const float cly = cy - ry, chy = cy + ry;
    const float area_g = (gx2 - gx1) * (gy2 - gy1);

    unsigned long long bk[TOPK];
#pragma unroll
    for (int j = 0; j < TOPK; j++) bk[j] = SENT;
    int cnt = 0;

    const float2* ap2  = (const float2*)anchor_points;
    const float4* pb4  = (const float4*)pred_bboxes;
    const float*  crow = g_clsT + (size_t)L * A_N;

#pragma unroll 4
    for (int a = tid; a < A_N; a += NT) {
        float2 ap  = __ldg(ap2 + a);
        float4 pb  = __ldg(pb4 + a);
        float  cls = __ldg(crow + a);

        bool inside = (ap.x >= gx1) & (ap.x <= gx2) & (ap.y >= gy1) & (ap.y <= gy2)
                    & (ap.x >= clx) & (ap.x <= chx) & (ap.y >= cly) & (ap.y <= chy);

        float w  = fmaxf(fminf(pb.z, gx2) - fmaxf(pb.x, gx1), 0.0f);
        float h  = fmaxf(fminf(pb.w, gy2) - fmaxf(pb.y, gy1), 0.0f);
        float ov = w * h;
        cnt += (inside && ov > 0.0f);

        // exact lower bound: cost >= cls + mask  (3*iou_cost >= 0, rn-add monotone)
        float lb = __fadd_rn(cls, inside ? 0.0f : 1e10f);
        unsigned long long klb = packKey(lb, (unsigned)a);
        if (klb <= bk[TOPK - 1]) {
            float area_p = (pb.z - pb.x) * (pb.w - pb.y);
            float iou  = ov / (area_p + area_g - ov + 1e-6f);
            float iouc = -logf(fmaxf(iou, 1e-7f));
            float cost = __fadd_rn(__fadd_rn(cls, __fmul_rn(3.0f, iouc)),
                                   inside ? 0.0f : 1e10f);
            unsigned long long k = packKey(cost, (unsigned)a);
            if (k < bk[TOPK - 1]) {
                bk[TOPK - 1] = k;
#pragma unroll
                for (int j = TOPK - 1; j > 0; j--) {
                    bool sw = bk[j] < bk[j - 1];
                    unsigned long long lo = sw ? bk[j] : bk[j - 1];
                    unsigned long long hi = sw ? bk[j - 1] : bk[j];
                    bk[j - 1] = lo; bk[j] = hi;
                }
            }
        }
    }

    // ---- block merge: NT threads x sorted top-10 -> global top-10 ----
    __shared__ unsigned long long skeys[NT * TOPK];
    __shared__ unsigned long long swmin[NT / 32];
    __shared__ int scnt[NT / 32];
    __shared__ unsigned long long s_winner;
    __shared__ int s_topk[TOPK];
    __shared__ int s_k;

#pragma unroll
    for (int j = 0; j < TOPK; j++) skeys[tid * TOPK + j] = bk[j];

    int lane = tid & 31, wid = tid >> 5;
    int c = cnt;
    for (int o = 16; o; o >>= 1) c += __shfl_down_sync(0xffffffffu, c, o);
    if (lane == 0) scnt[wid] = c;
    __syncthreads();
    if (tid == 0) {
        int s = 0;
        for (int i = 0; i < NT / 32; i++) s += scnt[i];
        s_k = (s < 1) ? 1 : ((s > TOPK) ? TOPK : s);
    }

    int p = 0;
    for (int r = 0; r < TOPK; r++) {
        unsigned long long cand = (p < TOPK) ? skeys[tid * TOPK + p] : SENT;
        unsigned long long m = cand;
        for (int o = 16; o; o >>= 1) {
            unsigned long long other = __shfl_down_sync(0xffffffffu, m, o);
            m = (other < m) ? other : m;
        }
        if (lane == 0) swmin[wid] = m;
        __syncthreads();
        if (tid == 0) {
            unsigned long long w = swmin[0];
            for (int i = 1; i < NT / 32; i++) if (swmin[i] < w) w = swmin[i];
            s_winner = w;
            s_topk[r] = (int)(w & 0xffffffffu);
        }
        __syncthreads();
        if (cand == s_winner) p++;
    }

    if (tid < s_k) atomicMax(&g_assigned[s_topk[tid]], g);
}

// ---- kernel 4: finalize outputs ----
__global__ void finalize_kernel(const float* __restrict__ pred_bboxes,
                                const int*   __restrict__ gt_labels,
                                const float* __restrict__ gt_bboxes,
                                float* __restrict__ out)
{
    int a = blockIdx.x * blockDim.x + threadIdx.x;
    if (a >= A_N) return;

    int  g    = g_assigned[a];
    bool pos  = (g >= 0);
    int  safe = pos ? g : 0;
    int  label = pos ? gt_labels[safe] : C_N;

    float4 gbx = ((const float4*)gt_bboxes)[safe];

    out[a] = (float)label;

    float* ob = out + A_N + (size_t)a * 4;
    ob[0] = pos ? gbx.x : 0.0f;
    ob[1] = pos ? gbx.y : 0.0f;
    ob[2] = pos ? gbx.z : 0.0f;
    ob[3] = pos ? gbx.w : 0.0f;

    float sc_val = 0.0f;
    if (pos) {
        float4 pb = ((const float4*)pred_bboxes)[a];
        float ltx = fmaxf(pb.x, gbx.x), lty = fmaxf(pb.y, gbx.y);
        float rbx = fminf(pb.z, gbx.z), rby = fminf(pb.w, gbx.w);
        float w = fmaxf(rbx - ltx, 0.0f);
        float h = fmaxf(rby - lty, 0.0f);
        float ov = w * h;
        float area_p = (pb.z - pb.x) * (pb.w - pb.y);
        float area_g = (gbx.z - gbx.x) * (gbx.w - gbx.y);
        sc_val = ov / (area_p + area_g - ov + 1e-6f);
    }
    float* os = out + (size_t)5 * A_N + (size_t)a * (C_N + 1);
#pragma unroll 9
    for (int c = 0; c <= C_N; c++) os[c] = 0.0f;
    if (pos) os[label] = sc_val;
}

extern "C" void kernel_launch(void* const* d_in, const int* in_sizes, int n_in,
                              void* d_out, int out_size) {
    const float* pred_scores   = (const float*)d_in[0];
    const float* pred_bboxes   = (const float*)d_in[1];
    const float* anchor_points = (const float*)d_in[2];
    const int*   gt_labels     = (const int*)  d_in[3];
    const float* gt_bboxes     = (const float*)d_in[4];
    float* out = (float*)d_out;

    totalneg_kernel<<<(A_N * 32 + 255) / 256, 256>>>(pred_scores);
    clsT_kernel<<<dim3(A_N / 32, (C_N + 31) / 32), dim3(32, 32)>>>(pred_scores);
    simota_kernel<<<G_N, NT>>>(pred_bboxes, anchor_points, gt_labels, gt_bboxes);
    finalize_kernel<<<(A_N + 255) / 256, 256>>>(pred_bboxes, gt_labels, gt_bboxes, out);
}